// round 12
// baseline (speedup 1.0000x reference)
#include <cuda_runtime.h>
#include <cstdint>

// Shapes fixed by reference: B=8, N=8192 -> 65536 points, D=64, F=64
#define TOTAL_POINTS 65536
#define NCHUNKS (TOTAL_POINTS / 2)   // CHUNK = 2 points
#define THREADS 256
#define GRID 2048                     // 32768/2048 = 16 chunks per block exactly

typedef unsigned long long ull;

__device__ __forceinline__ void fma2(ull &acc, ull a, ull b) {
    asm("fma.rn.f32x2 %0, %1, %2, %0;" : "+l"(acc) : "l"(a), "l"(b));
}
__device__ __forceinline__ ull add2(ull a, ull b) {
    ull r; asm("add.rn.f32x2 %0, %1, %2;" : "=l"(r) : "l"(a), "l"(b)); return r;
}
__device__ __forceinline__ ull dup2(float w) {
    ull r; asm("mov.b64 %0, {%1, %1};" : "=l"(r) : "r"(__float_as_uint(w))); return r;
}
__device__ __forceinline__ float lo32(ull v) { return __uint_as_float((unsigned)v); }
__device__ __forceinline__ float hi32(ull v) { return __uint_as_float((unsigned)(v >> 32)); }

__global__ void __launch_bounds__(THREADS, 2)
affine_linear_kernel(const float* __restrict__ X, const float* __restrict__ J,
                     const float* __restrict__ A, const float* __restrict__ Bm,
                     const float* __restrict__ C, float* __restrict__ Y)
{
    // T layout: [e(192)][i(3)][p(2)] floats; index = e*6 + i*2 + p
    __shared__ float T_s[192 * 6];

    const int tid = threadIdx.x;
    const int w = tid >> 5;     // warp 0..7 owns output rows 8w..8w+7
    const int g = tid & 31;     // e-partition lane: e = 32j + g

    // W = [A | Bm | C] : 8 rows x 6 e-columns per thread, in registers (48 floats)
    // j=0: A[.,g]  j=1: A[.,32+g]  j=2: Bm[.,g]  j=3: Bm[.,32+g]  j=4: C[.,g]  j=5: C[.,32+g]
    float Wf[48];
#pragma unroll
    for (int r = 0; r < 8; ++r) {
        const int f = 8 * w + r;
        Wf[r * 6 + 0] = A [f * 64 + g];
        Wf[r * 6 + 1] = A [f * 64 + 32 + g];
        Wf[r * 6 + 2] = Bm[f * 64 + g];
        Wf[r * 6 + 3] = Bm[f * 64 + 32 + g];
        Wf[r * 6 + 4] = C [f * 64 + g];
        Wf[r * 6 + 5] = C [f * 64 + 32 + g];
    }

    // Phase A mapping (threads 0..127 only): d = frame idx, p = point in chunk
    const int d = (tid & 127) >> 1;
    const int p = tid & 1;
    const bool phaseA = tid < 128;

    int c = blockIdx.x;

    // Prologue: load first chunk's J/X
    float j0, j1, j2, j3, j4, j5, x0, x1, x2;
    if (phaseA) {
        size_t pt = (size_t)c * 2 + p;
        const float* Jp = J + (pt * 64 + d) * 6;
        float2 ja = *(const float2*)(Jp + 0);
        float2 jb = *(const float2*)(Jp + 2);
        float2 jc = *(const float2*)(Jp + 4);
        j0 = ja.x; j1 = ja.y; j2 = jb.x; j3 = jb.y; j4 = jc.x; j5 = jc.y;
        const float* Xp = X + (pt * 64 + d) * 3;
        x0 = Xp[0]; x1 = Xp[1]; x2 = Xp[2];
    }

    for (; c < NCHUNKS; c += GRID) {
        // ---------------- Phase A: frames + term construction ----------------
        if (phaseA) {
            float a1x = j0, a1y = j2, a1z = j4;
            float a2x = j1, a2y = j3, a2z = j5;
            float n1 = a1x * a1x + a1y * a1y + a1z * a1z;
            float s1 = rsqrtf(fmaxf(n1, 1e-24f));
            float b1x = a1x * s1, b1y = a1y * s1, b1z = a1z * s1;
            float dt = b1x * a2x + b1y * a2y + b1z * a2z;
            float ux = a2x - dt * b1x, uy = a2y - dt * b1y, uz = a2z - dt * b1z;
            float s2 = rsqrtf(fmaxf(ux * ux + uy * uy + uz * uz, 1e-24f));
            float b2x = ux * s2, b2y = uy * s2, b2z = uz * s2;
            float b3x = b1y * b2z - b1z * b2y;
            float b3y = b1z * b2x - b1x * b2z;
            float b3z = b1x * b2y - b1y * b2x;
            float rt0 = b1x * x0 + b1y * x1 + b1z * x2;
            float rt1 = b2x * x0 + b2y * x1 + b2z * x2;
            float rt2 = b3x * x0 + b3y * x1 + b3z * x2;

            // STS (conflict-free: bank = (6d + 2i + p) mod 32, all distinct per warp)
            float* Ta = &T_s[(d)       * 6 + p];
            float* Tb = &T_s[(64 + d)  * 6 + p];
            float* Tc = &T_s[(128 + d) * 6 + p];
            Ta[0] = b1x * rt0 + b2x * rt1;  Ta[2] = b1y * rt0 + b2y * rt1;  Ta[4] = b1z * rt0 + b2z * rt1;
            Tb[0] = b2x * rt0 - b1x * rt1;  Tb[2] = b2y * rt0 - b1y * rt1;  Tb[4] = b2z * rt0 - b1z * rt1;
            Tc[0] = b3x * rt2;              Tc[2] = b3y * rt2;              Tc[4] = b3z * rt2;
        }
        __syncthreads();

        // Prefetch next chunk's J/X (hidden under the GEMM)
        int cn = c + GRID;
        if (phaseA && cn < NCHUNKS) {
            size_t pt = (size_t)cn * 2 + p;
            const float* Jp = J + (pt * 64 + d) * 6;
            float2 ja = *(const float2*)(Jp + 0);
            float2 jb = *(const float2*)(Jp + 2);
            float2 jc = *(const float2*)(Jp + 4);
            j0 = ja.x; j1 = ja.y; j2 = jb.x; j3 = jb.y; j4 = jc.x; j5 = jc.y;
            const float* Xp = X + (pt * 64 + d) * 3;
            x0 = Xp[0]; x1 = Xp[1]; x2 = Xp[2];
        }

        // ------- Phase B: 8 rows/thread, e = 32j + g, acc packs (p0,p1) -------
        ull acc[24];
#pragma unroll
        for (int k = 0; k < 24; ++k) acc[k] = 0ull;
#pragma unroll
        for (int j = 0; j < 6; ++j) {
            const float* tp = &T_s[(32 * j + g) * 6];
            ull t0 = *(const ull*)(tp + 0);
            ull t1 = *(const ull*)(tp + 2);
            ull t2 = *(const ull*)(tp + 4);
#pragma unroll
            for (int r = 0; r < 8; ++r) {
                ull wv = dup2(Wf[r * 6 + j]);
                fma2(acc[r * 3 + 0], wv, t0);
                fma2(acc[r * 3 + 1], wv, t1);
                fma2(acc[r * 3 + 2], wv, t2);
            }
        }

        // ---- Collapsing reduction over 32 e-lanes ----
        // Round 1 (xor 16): rows 8 -> 4
        {
            const bool b = (g & 16) != 0;
#pragma unroll
            for (int k = 0; k < 12; ++k) {
                ull give = b ? acc[k] : acc[k + 12];
                ull got  = __shfl_xor_sync(0xffffffffu, give, 16);
                ull keep = b ? acc[k + 12] : acc[k];
                acc[k] = add2(keep, got);
            }
        }
        // Round 2 (xor 8): rows 4 -> 2
        {
            const bool b = (g & 8) != 0;
#pragma unroll
            for (int k = 0; k < 6; ++k) {
                ull give = b ? acc[k] : acc[k + 6];
                ull got  = __shfl_xor_sync(0xffffffffu, give, 8);
                ull keep = b ? acc[k + 6] : acc[k];
                acc[k] = add2(keep, got);
            }
        }
        // Round 3 (xor 4): rows 2 -> 1
        {
            const bool b = (g & 4) != 0;
#pragma unroll
            for (int k = 0; k < 3; ++k) {
                ull give = b ? acc[k] : acc[k + 3];
                ull got  = __shfl_xor_sync(0xffffffffu, give, 4);
                ull keep = b ? acc[k + 3] : acc[k];
                acc[k] = add2(keep, got);
            }
        }
        // Rounds 4,5 (xor 2, xor 1): plain
#pragma unroll
        for (int k = 0; k < 3; ++k)
            acc[k] = add2(acc[k], __shfl_xor_sync(0xffffffffu, acc[k], 2));
#pragma unroll
        for (int k = 0; k < 3; ++k)
            acc[k] = add2(acc[k], __shfl_xor_sync(0xffffffffu, acc[k], 1));

        // Store: lanes g = 0,4,...,28 hold row r_local = bits{g4,g3,g2}
        if ((g & 3) == 0) {
            const int r_local = ((g >> 4) & 1) * 4 + ((g >> 3) & 1) * 2 + ((g >> 2) & 1);
            const int f = 8 * w + r_local;
            size_t base0 = (size_t)c * 2 * 192 + f * 3;
            Y[base0 + 0]   = lo32(acc[0]);
            Y[base0 + 1]   = lo32(acc[1]);
            Y[base0 + 2]   = lo32(acc[2]);
            Y[base0 + 192] = hi32(acc[0]);
            Y[base0 + 193] = hi32(acc[1]);
            Y[base0 + 194] = hi32(acc[2]);
        }
        __syncthreads();
    }
}

extern "C" void kernel_launch(void* const* d_in, const int* in_sizes, int n_in,
                              void* d_out, int out_size) {
    // metadata order: X, J, A, Bm, C
    const float* X  = (const float*)d_in[0];
    const float* J  = (const float*)d_in[1];
    const float* A  = (const float*)d_in[2];
    const float* Bm = (const float*)d_in[3];
    const float* C  = (const float*)d_in[4];
    float* Y = (float*)d_out;
    affine_linear_kernel<<<GRID, THREADS>>>(X, J, A, Bm, C, Y);
}

// round 13
// speedup vs baseline: 1.0131x; 1.0131x over previous
#include <cuda_runtime.h>
#include <cstdint>

// Shapes fixed by reference: B=8, N=8192 -> 65536 points, D=64, F=64
#define TOTAL_POINTS 65536
#define NCHUNKS (TOTAL_POINTS / 2)   // CHUNK = 2 points
#define THREADS 256
#define GRID 2048                     // 32768/2048 = 16 chunks per block exactly

typedef unsigned long long ull;

__device__ __forceinline__ void fma2(ull &acc, ull a, ull b) {
    asm("fma.rn.f32x2 %0, %1, %2, %0;" : "+l"(acc) : "l"(a), "l"(b));
}
__device__ __forceinline__ ull add2(ull a, ull b) {
    ull r; asm("add.rn.f32x2 %0, %1, %2;" : "=l"(r) : "l"(a), "l"(b)); return r;
}
__device__ __forceinline__ ull dup2(float w) {
    ull r; asm("mov.b64 %0, {%1, %1};" : "=l"(r) : "r"(__float_as_uint(w))); return r;
}
__device__ __forceinline__ float lo32(ull v) { return __uint_as_float((unsigned)v); }
__device__ __forceinline__ float hi32(ull v) { return __uint_as_float((unsigned)(v >> 32)); }

__global__ void __launch_bounds__(THREADS, 2)
affine_linear_kernel(const float* __restrict__ X, const float* __restrict__ J,
                     const float* __restrict__ A, const float* __restrict__ Bm,
                     const float* __restrict__ C, float* __restrict__ Y)
{
    // T layout: [e(192)][i(3)][p(2)] floats; index = e*6 + i*2 + p
    __shared__ float T_s[192 * 6];

    const int tid = threadIdx.x;
    const int w = tid >> 5;     // warp 0..7 owns output rows 8w..8w+7
    const int g = tid & 31;     // e-partition lane: e = 32j + g

    // W = [A | Bm | C] : 8 rows x 6 e-columns per thread, in registers (48 floats)
    // j=0: A[.,g]  j=1: A[.,32+g]  j=2: Bm[.,g]  j=3: Bm[.,32+g]  j=4: C[.,g]  j=5: C[.,32+g]
    float Wf[48];
#pragma unroll
    for (int r = 0; r < 8; ++r) {
        const int f = 8 * w + r;
        Wf[r * 6 + 0] = A [f * 64 + g];
        Wf[r * 6 + 1] = A [f * 64 + 32 + g];
        Wf[r * 6 + 2] = Bm[f * 64 + g];
        Wf[r * 6 + 3] = Bm[f * 64 + 32 + g];
        Wf[r * 6 + 4] = C [f * 64 + g];
        Wf[r * 6 + 5] = C [f * 64 + 32 + g];
    }

    // Phase A mapping (threads 0..127 only): d = frame idx, p = point in chunk
    const int d = (tid & 127) >> 1;
    const int p = tid & 1;
    const bool phaseA = tid < 128;

    int c = blockIdx.x;

    // Prologue: load first chunk's J/X
    float j0, j1, j2, j3, j4, j5, x0, x1, x2;
    if (phaseA) {
        size_t pt = (size_t)c * 2 + p;
        const float* Jp = J + (pt * 64 + d) * 6;
        float2 ja = *(const float2*)(Jp + 0);
        float2 jb = *(const float2*)(Jp + 2);
        float2 jc = *(const float2*)(Jp + 4);
        j0 = ja.x; j1 = ja.y; j2 = jb.x; j3 = jb.y; j4 = jc.x; j5 = jc.y;
        const float* Xp = X + (pt * 64 + d) * 3;
        x0 = Xp[0]; x1 = Xp[1]; x2 = Xp[2];
    }

    for (; c < NCHUNKS; c += GRID) {
        // ---------------- Phase A: frames + term construction ----------------
        if (phaseA) {
            float a1x = j0, a1y = j2, a1z = j4;
            float a2x = j1, a2y = j3, a2z = j5;
            float n1 = a1x * a1x + a1y * a1y + a1z * a1z;
            float s1 = rsqrtf(fmaxf(n1, 1e-24f));
            float b1x = a1x * s1, b1y = a1y * s1, b1z = a1z * s1;
            float dt = b1x * a2x + b1y * a2y + b1z * a2z;
            float ux = a2x - dt * b1x, uy = a2y - dt * b1y, uz = a2z - dt * b1z;
            float s2 = rsqrtf(fmaxf(ux * ux + uy * uy + uz * uz, 1e-24f));
            float b2x = ux * s2, b2y = uy * s2, b2z = uz * s2;
            float b3x = b1y * b2z - b1z * b2y;
            float b3y = b1z * b2x - b1x * b2z;
            float b3z = b1x * b2y - b1y * b2x;
            float rt0 = b1x * x0 + b1y * x1 + b1z * x2;
            float rt1 = b2x * x0 + b2y * x1 + b2z * x2;
            float rt2 = b3x * x0 + b3y * x1 + b3z * x2;

            // STS (conflict-free: bank = (6d + 2i + p) mod 32, all distinct per warp)
            float* Ta = &T_s[(d)       * 6 + p];
            float* Tb = &T_s[(64 + d)  * 6 + p];
            float* Tc = &T_s[(128 + d) * 6 + p];
            Ta[0] = b1x * rt0 + b2x * rt1;  Ta[2] = b1y * rt0 + b2y * rt1;  Ta[4] = b1z * rt0 + b2z * rt1;
            Tb[0] = b2x * rt0 - b1x * rt1;  Tb[2] = b2y * rt0 - b1y * rt1;  Tb[4] = b2z * rt0 - b1z * rt1;
            Tc[0] = b3x * rt2;              Tc[2] = b3y * rt2;              Tc[4] = b3z * rt2;
        }
        __syncthreads();

        // Prefetch next chunk's J/X (hidden under the GEMM)
        int cn = c + GRID;
        if (phaseA && cn < NCHUNKS) {
            size_t pt = (size_t)cn * 2 + p;
            const float* Jp = J + (pt * 64 + d) * 6;
            float2 ja = *(const float2*)(Jp + 0);
            float2 jb = *(const float2*)(Jp + 2);
            float2 jc = *(const float2*)(Jp + 4);
            j0 = ja.x; j1 = ja.y; j2 = jb.x; j3 = jb.y; j4 = jc.x; j5 = jc.y;
            const float* Xp = X + (pt * 64 + d) * 3;
            x0 = Xp[0]; x1 = Xp[1]; x2 = Xp[2];
        }

        // ------- Phase B: 8 rows/thread, e = 32j + g, acc packs (p0,p1) -------
        ull acc[24];
#pragma unroll
        for (int k = 0; k < 24; ++k) acc[k] = 0ull;
#pragma unroll
        for (int j = 0; j < 6; ++j) {
            const float* tp = &T_s[(32 * j + g) * 6];
            ull t0 = *(const ull*)(tp + 0);
            ull t1 = *(const ull*)(tp + 2);
            ull t2 = *(const ull*)(tp + 4);
#pragma unroll
            for (int r = 0; r < 8; ++r) {
                ull wv = dup2(Wf[r * 6 + j]);
                fma2(acc[r * 3 + 0], wv, t0);
                fma2(acc[r * 3 + 1], wv, t1);
                fma2(acc[r * 3 + 2], wv, t2);
            }
        }

        // ---- Collapsing reduction over 32 e-lanes ----
        // Round 1 (xor 16): rows 8 -> 4
        {
            const bool b = (g & 16) != 0;
#pragma unroll
            for (int k = 0; k < 12; ++k) {
                ull give = b ? acc[k] : acc[k + 12];
                ull got  = __shfl_xor_sync(0xffffffffu, give, 16);
                ull keep = b ? acc[k + 12] : acc[k];
                acc[k] = add2(keep, got);
            }
        }
        // Round 2 (xor 8): rows 4 -> 2
        {
            const bool b = (g & 8) != 0;
#pragma unroll
            for (int k = 0; k < 6; ++k) {
                ull give = b ? acc[k] : acc[k + 6];
                ull got  = __shfl_xor_sync(0xffffffffu, give, 8);
                ull keep = b ? acc[k + 6] : acc[k];
                acc[k] = add2(keep, got);
            }
        }
        // Round 3 (xor 4): rows 2 -> 1
        {
            const bool b = (g & 4) != 0;
#pragma unroll
            for (int k = 0; k < 3; ++k) {
                ull give = b ? acc[k] : acc[k + 3];
                ull got  = __shfl_xor_sync(0xffffffffu, give, 4);
                ull keep = b ? acc[k + 3] : acc[k];
                acc[k] = add2(keep, got);
            }
        }
        // Rounds 4,5 (xor 2, xor 1): plain
#pragma unroll
        for (int k = 0; k < 3; ++k)
            acc[k] = add2(acc[k], __shfl_xor_sync(0xffffffffu, acc[k], 2));
#pragma unroll
        for (int k = 0; k < 3; ++k)
            acc[k] = add2(acc[k], __shfl_xor_sync(0xffffffffu, acc[k], 1));

        // Store: lanes g = 0,4,...,28 hold row r_local = bits{g4,g3,g2}
        if ((g & 3) == 0) {
            const int r_local = ((g >> 4) & 1) * 4 + ((g >> 3) & 1) * 2 + ((g >> 2) & 1);
            const int f = 8 * w + r_local;
            size_t base0 = (size_t)c * 2 * 192 + f * 3;
            Y[base0 + 0]   = lo32(acc[0]);
            Y[base0 + 1]   = lo32(acc[1]);
            Y[base0 + 2]   = lo32(acc[2]);
            Y[base0 + 192] = hi32(acc[0]);
            Y[base0 + 193] = hi32(acc[1]);
            Y[base0 + 194] = hi32(acc[2]);
        }
        __syncthreads();
    }
}

extern "C" void kernel_launch(void* const* d_in, const int* in_sizes, int n_in,
                              void* d_out, int out_size) {
    // metadata order: X, J, A, Bm, C
    const float* X  = (const float*)d_in[0];
    const float* J  = (const float*)d_in[1];
    const float* A  = (const float*)d_in[2];
    const float* Bm = (const float*)d_in[3];
    const float* C  = (const float*)d_in[4];
    float* Y = (float*)d_out;
    affine_linear_kernel<<<GRID, THREADS>>>(X, J, A, Bm, C, Y);
}